// round 2
// baseline (speedup 1.0000x reference)
#include <cuda_runtime.h>

// Inputs (metadata order):
// 0: y      (B, 4N) = (256, 512) f32
// 1: Ic     (B,)    f32
// 2: C      (N,)    f32
// 3: g_Na   (N,)
// 4: E_Na   (N,)
// 5: g_K    (N,)
// 6: E_K    (N,)
// 7: g_L    (N,)
// 8: E_L    (N,)
// 9: m_inf  (N,)
// 10: tau_m (N,)
// 11: h_inf (N,)
// 12: tau_h (N,)
// 13: n_inf (N,)
// 14: tau_n (N,)
// 15: g_C   (N, N)
// Output: ydot (B,4N) followed by J (B,4N,4N), f32.

#define BATCH 256
#define NN    128   // N
#define E4    512   // 4*N

__device__ float g_S;  // sum over all (i,j) of g_C[i,j] / C[j]

// ---------------------------------------------------------------------------
// Kernel 0: scalar reduction S = sum_{i,j} g_C[i,j] * invC[j]
// ---------------------------------------------------------------------------
__global__ void s_kernel(const float* __restrict__ gC, const float* __restrict__ C) {
    __shared__ float invC[NN];
    __shared__ float red[8];
    int tid = threadIdx.x;
    if (tid < NN) invC[tid] = 1.0f / C[tid];
    __syncthreads();

    float acc = 0.0f;
    for (int t = tid; t < NN * NN; t += blockDim.x)
        acc += gC[t] * invC[t & (NN - 1)];

    // warp reduce
    #pragma unroll
    for (int o = 16; o > 0; o >>= 1)
        acc += __shfl_xor_sync(0xFFFFFFFFu, acc, o);
    if ((tid & 31) == 0) red[tid >> 5] = acc;
    __syncthreads();
    if (tid == 0) {
        float s = 0.0f;
        int nw = blockDim.x / 32;
        for (int w = 0; w < nw; w++) s += red[w];
        g_S = s;
    }
}

// ---------------------------------------------------------------------------
// Kernel 1: ydot.  grid = BATCH blocks, 128 threads (one per neuron).
// ---------------------------------------------------------------------------
__global__ void ydot_kernel(
    const float* __restrict__ y, const float* __restrict__ Ic,
    const float* __restrict__ C,
    const float* __restrict__ gNa, const float* __restrict__ ENa,
    const float* __restrict__ gK,  const float* __restrict__ EK,
    const float* __restrict__ gL,  const float* __restrict__ EL,
    const float* __restrict__ minf, const float* __restrict__ taum,
    const float* __restrict__ hinf, const float* __restrict__ tauh,
    const float* __restrict__ ninf, const float* __restrict__ taun,
    const float* __restrict__ gC,
    float* __restrict__ out)
{
    __shared__ float Vs[NN];
    __shared__ float Wj[NN];   // invC[j]

    int b = blockIdx.x;
    int i = threadIdx.x;

    float4 y4 = reinterpret_cast<const float4*>(y)[b * NN + i];
    float V = y4.x, m = y4.y, h = y4.z, n = y4.w;
    float invCi = 1.0f / C[i];
    Vs[i] = V;
    Wj[i] = invCi;
    __syncthreads();

    // coupling: sum_j gC[i,j] * invC[j] * (V_i - V_j)
    float acc = 0.0f;
    const float* gCrow = gC + i * NN;
    #pragma unroll 8
    for (int j = 0; j < NN; j++)
        acc += gCrow[j] * Wj[j] * (V - Vs[j]);

    float m2 = m * m, m3 = m2 * m;
    float n2 = n * n, n4 = n2 * n2;
    float Vdot = invCi * (-gNa[i] * m3 * h * (V - ENa[i])
                          - gK[i] * n4 * (V - EK[i])
                          - gL[i] * (V - EL[i])
                          + Ic[b]) + acc;
    float mdot = (minf[i] - m) / taum[i];
    float hdot = (hinf[i] - h) / tauh[i];
    float ndot = (ninf[i] - n) / taun[i];

    float4 o;
    o.x = Vdot; o.y = mdot; o.z = hdot; o.w = ndot;
    reinterpret_cast<float4*>(out)[b * NN + i] = o;
}

// ---------------------------------------------------------------------------
// Kernel 2: fill J.  One float4 per thread (columns 4j..4j+3 of row r, batch b).
// total float4 = BATCH * 512 * 128 = 16,777,216.
// idx layout: j = idx & 127; r = (idx >> 7) & 511; b = idx >> 16.
// ---------------------------------------------------------------------------
__global__ void jfill_kernel(
    const float* __restrict__ y,
    const float* __restrict__ C,
    const float* __restrict__ gNa, const float* __restrict__ ENa,
    const float* __restrict__ gK,  const float* __restrict__ EK,
    const float* __restrict__ gL,
    const float* __restrict__ taum, const float* __restrict__ tauh,
    const float* __restrict__ taun,
    const float* __restrict__ gC,
    float* __restrict__ J)
{
    int idx = blockIdx.x * blockDim.x + threadIdx.x;
    int j = idx & (NN - 1);
    int r = (idx >> 7) & (E4 - 1);
    int b = idx >> 16;

    int rt = r & 3;        // warp-uniform
    int i  = r >> 2;

    float4 v = make_float4(0.f, 0.f, 0.f, 0.f);

    if (rt == 0) {
        // V row: v.x = JVV[i,j]; diag-only entries in y/z/w when i==j
        float invCj = 1.0f / C[j];
        float gc = gC[i * NN + j];
        v.x = -gc * invCj;
        if (i == j) {
            float4 y4 = reinterpret_cast<const float4*>(y)[b * NN + i];
            float V = y4.x, m = y4.y, h = y4.z, n = y4.w;
            float invCi = invCj;  // i == j
            float m2 = m * m, m3 = m2 * m;
            float n2 = n * n, n3 = n2 * n, n4 = n3 * n;
            float ga = gNa[i], gk = gK[i];
            float dNa = V - ENa[i], dK = V - EK[i];
            v.x += g_S + invCi * (-gL[i] - ga * h * m3 - gk * n4);
            v.y = -invCi * (3.0f * ga * h * m2 * dNa);
            v.z = -invCi * (ga * m3 * dNa);
            v.w = -invCi * (4.0f * gk * n3 * dK);
        }
    } else if (i == j) {
        float t = (rt == 1) ? taum[i] : (rt == 2) ? tauh[i] : taun[i];
        float val = -1.0f / t;
        if (rt == 1) v.y = val;
        else if (rt == 2) v.z = val;
        else v.w = val;
    }

    reinterpret_cast<float4*>(J)[idx] = v;
}

// ---------------------------------------------------------------------------
extern "C" void kernel_launch(void* const* d_in, const int* in_sizes, int n_in,
                              void* d_out, int out_size) {
    const float* y    = (const float*)d_in[0];
    const float* Ic   = (const float*)d_in[1];
    const float* C    = (const float*)d_in[2];
    const float* gNa  = (const float*)d_in[3];
    const float* ENa  = (const float*)d_in[4];
    const float* gK   = (const float*)d_in[5];
    const float* EK   = (const float*)d_in[6];
    const float* gL   = (const float*)d_in[7];
    const float* EL   = (const float*)d_in[8];
    const float* minf = (const float*)d_in[9];
    const float* taum = (const float*)d_in[10];
    const float* hinf = (const float*)d_in[11];
    const float* tauh = (const float*)d_in[12];
    const float* ninf = (const float*)d_in[13];
    const float* taun = (const float*)d_in[14];
    const float* gC   = (const float*)d_in[15];

    float* out_ydot = (float*)d_out;
    float* out_J    = out_ydot + BATCH * E4;

    s_kernel<<<1, 256>>>(gC, C);
    ydot_kernel<<<BATCH, NN>>>(y, Ic, C, gNa, ENa, gK, EK, gL, EL,
                               minf, taum, hinf, tauh, ninf, taun, gC, out_ydot);
    const int total4 = BATCH * E4 * NN;  // 16,777,216 float4
    jfill_kernel<<<total4 / 256, 256>>>(y, C, gNa, ENa, gK, EK, gL,
                                        taum, tauh, taun, gC, out_J);
}